// round 8
// baseline (speedup 1.0000x reference)
#include <cuda_runtime.h>
#include <cuda_bf16.h>
#include <cuda_fp16.h>
#include <math.h>
#include <cstdint>

#define S_LEN 2048
#define HID   4096
#define NH    32
#define NKV   8
#define HD    128

// ---------------- scratch (static device globals; no allocations) -----------
__device__ float g_Q [S_LEN * NH  * HD];
__device__ float g_K [S_LEN * NKV * HD];

__device__ __nv_bfloat16 g_hs_hi[S_LEN * HID],      g_hs_lo[S_LEN * HID];
__device__ __nv_bfloat16 g_wq_hi[HID * HID],        g_wq_lo[HID * HID];
__device__ __nv_bfloat16 g_wk_hi[NKV * HD * HID],   g_wk_lo[NKV * HD * HID];
__device__ __nv_bfloat16 g_wv_hi[NKV * HD * HID],   g_wv_lo[NKV * HD * HID];
__device__ __nv_bfloat16 g_wo_hi[HID * HID],        g_wo_lo[HID * HID];
__device__ __nv_bfloat16 g_ao_hi[S_LEN * HID],      g_ao_lo[S_LEN * HID];
__device__ __nv_bfloat16 g_q_hi[S_LEN * NH  * HD],  g_q_lo[S_LEN * NH  * HD];
__device__ __nv_bfloat16 g_k_hi[S_LEN * NKV * HD],  g_k_lo[S_LEN * NKV * HD];
__device__ __half        g_v_hi[S_LEN * NKV * HD],  g_v_lo[S_LEN * NKV * HD];

// ---------------- common PTX helpers ----------------------------------------
__device__ __forceinline__ uint32_t smem_u32(const void* p) {
    uint32_t a;
    asm("{ .reg .u64 t; cvta.to.shared.u64 t, %1; cvt.u32.u64 %0, t; }" : "=r"(a) : "l"(p));
    return a;
}
__device__ __forceinline__ void cp16(uint32_t dst, const void* src) {
    asm volatile("cp.async.cg.shared.global [%0], [%1], 16;" :: "r"(dst), "l"(src) : "memory");
}
#define CP_COMMIT() asm volatile("cp.async.commit_group;" ::: "memory")
template <int N> __device__ __forceinline__ void cp_wait() {
    asm volatile("cp.async.wait_group %0;" :: "n"(N) : "memory");
}
__device__ __forceinline__ void ldmx4(uint32_t* r, uint32_t addr) {
    asm volatile("ldmatrix.sync.aligned.m8n8.x4.shared.b16 {%0,%1,%2,%3}, [%4];"
                 : "=r"(r[0]), "=r"(r[1]), "=r"(r[2]), "=r"(r[3]) : "r"(addr));
}
__device__ __forceinline__ void ldmx4t(uint32_t* r, uint32_t addr) {
    asm volatile("ldmatrix.sync.aligned.m8n8.x4.trans.shared.b16 {%0,%1,%2,%3}, [%4];"
                 : "=r"(r[0]), "=r"(r[1]), "=r"(r[2]), "=r"(r[3]) : "r"(addr));
}
__device__ __forceinline__ void mma16816(float* d, const uint32_t* a, uint32_t b0, uint32_t b1) {
    asm volatile(
        "mma.sync.aligned.m16n8k16.row.col.f32.bf16.bf16.f32 "
        "{%0,%1,%2,%3}, {%4,%5,%6,%7}, {%8,%9}, {%0,%1,%2,%3};"
        : "+f"(d[0]), "+f"(d[1]), "+f"(d[2]), "+f"(d[3])
        : "r"(a[0]), "r"(a[1]), "r"(a[2]), "r"(a[3]), "r"(b0), "r"(b1));
}
__device__ __forceinline__ void mma16816h(float* d, const uint32_t* a, uint32_t b0, uint32_t b1) {
    asm volatile(
        "mma.sync.aligned.m16n8k16.row.col.f32.f16.f16.f32 "
        "{%0,%1,%2,%3}, {%4,%5,%6,%7}, {%8,%9}, {%0,%1,%2,%3};"
        : "+f"(d[0]), "+f"(d[1]), "+f"(d[2]), "+f"(d[3])
        : "r"(a[0]), "r"(a[1]), "r"(a[2]), "r"(a[3]), "r"(b0), "r"(b1));
}
__device__ __forceinline__ uint32_t pack_bf16(float a, float b) {
    return ((uint32_t)__bfloat16_as_ushort(__float2bfloat16_rn(b)) << 16) |
           __bfloat16_as_ushort(__float2bfloat16_rn(a));
}
__device__ __forceinline__ void split_pack(float a, float b, uint32_t& hp, uint32_t& lp) {
    __nv_bfloat16 ha = __float2bfloat16_rn(a), hb = __float2bfloat16_rn(b);
    hp = ((uint32_t)__bfloat16_as_ushort(hb) << 16) | __bfloat16_as_ushort(ha);
    lp = pack_bf16(a - __bfloat162float(ha), b - __bfloat162float(hb));
}
__device__ __forceinline__ void split_pack_h(float a, float b, uint32_t& hp, uint32_t& lp) {
    __half ha = __float2half_rn(a), hb = __float2half_rn(b);
    hp = ((uint32_t)__half_as_ushort(hb) << 16) | __half_as_ushort(ha);
    __half la = __float2half_rn(a - __half2float(ha));
    __half lb = __float2half_rn(b - __half2float(hb));
    lp = ((uint32_t)__half_as_ushort(lb) << 16) | __half_as_ushort(la);
}
__device__ __forceinline__ float ex2f(float x) {
    float y;
    asm("ex2.approx.ftz.f32 %0, %1;" : "=f"(y) : "f"(x));
    return y;
}
__device__ __forceinline__ uint32_t ex2_f16x2(float a, float b) {
    uint32_t p;
    asm("cvt.rn.f16x2.f32 %0, %1, %2;" : "=r"(p) : "f"(b), "f"(a));
    asm("ex2.approx.f16x2 %0, %0;" : "+r"(p));
    return p;
}

// ---------------- split kernels ---------------------------------------------
__global__ void split_f32(const float4* __restrict__ x,
                          uint2* __restrict__ hi, uint2* __restrict__ lo, int n4) {
    int i = blockIdx.x * blockDim.x + threadIdx.x;
    if (i >= n4) return;
    float4 v = x[i];
    float xs[4] = {v.x, v.y, v.z, v.w};
    unsigned short h[4], l[4];
#pragma unroll
    for (int j = 0; j < 4; j++) {
        __nv_bfloat16 hb = __float2bfloat16_rn(xs[j]);
        float r = xs[j] - __bfloat162float(hb);
        h[j] = __bfloat16_as_ushort(hb);
        l[j] = __bfloat16_as_ushort(__float2bfloat16_rn(r));
    }
    hi[i] = make_uint2(((uint32_t)h[1] << 16) | h[0], ((uint32_t)h[3] << 16) | h[2]);
    lo[i] = make_uint2(((uint32_t)l[1] << 16) | l[0], ((uint32_t)l[3] << 16) | l[2]);
}

__global__ void rope_split(const float* __restrict__ X, const float* __restrict__ cosb,
                           const float* __restrict__ sinb,
                           __nv_bfloat16* __restrict__ hi, __nv_bfloat16* __restrict__ lo,
                           int nheads, float sc) {
    int idx = blockIdx.x * blockDim.x + threadIdx.x;
    int total = S_LEN * nheads * 32;
    if (idx >= total) return;
    int d = (idx & 31) * 2;
    int hh = (idx >> 5) % nheads;
    int s = idx / (32 * nheads);
    size_t base = (size_t)s * nheads * HD + hh * HD;
    float2 x1 = *(const float2*)(X + base + d);
    float2 x2 = *(const float2*)(X + base + d + 64);
    float2 c1 = *(const float2*)(cosb + s * HD + d);
    float2 s1 = *(const float2*)(sinb + s * HD + d);
    float2 c2 = *(const float2*)(cosb + s * HD + d + 64);
    float2 s2 = *(const float2*)(sinb + s * HD + d + 64);
    float o[4] = { (x1.x * c1.x - x2.x * s1.x) * sc, (x1.y * c1.y - x2.y * s1.y) * sc,
                   (x2.x * c2.x + x1.x * s2.x) * sc, (x2.y * c2.y + x1.y * s2.y) * sc };
    uint32_t hp0, lp0, hp1, lp1;
    split_pack(o[0], o[1], hp0, lp0);
    split_pack(o[2], o[3], hp1, lp1);
    *(uint32_t*)(hi + base + d)      = hp0;
    *(uint32_t*)(hi + base + d + 64) = hp1;
    *(uint32_t*)(lo + base + d)      = lp0;
    *(uint32_t*)(lo + base + d + 64) = lp1;
}

// =================== HMMA split-bf16 GEMM: CTA 128x256, warp 64x64 ==========
#define GBK 32
#define A_TILE 8192                     // 128 rows x 64 B
#define B_TILE 16384                    // 256 rows x 64 B
#define STAGE_BYTES (2 * A_TILE + 2 * B_TILE)   // 48 KB
#define GEMM_STAGES 3
#define GEMM_SMEM (GEMM_STAGES * STAGE_BYTES)   // 144 KB

__device__ __forceinline__ uint32_t swoff(int row, int kc) {
    return (uint32_t)(row * 64 + ((kc ^ ((row >> 1) & 3)) << 4));
}

struct GemmCore {
    uint32_t sb;
    int tid, lane, wm, wn;   // wm in {0,1} (64 M-rows each), wn in {0..3} (64 N-cols each)
    const __nv_bfloat16* gsrc[4];  // Ahi, Alo, Bhi, Blo

    __device__ __forceinline__ void prefetch(int c, int s) {
        uint32_t sbase = sb + s * STAGE_BYTES;
        // A hi/lo: 128 rows x 4 kc = 512 cp16 each
#pragma unroll
        for (int t = 0; t < 2; t++) {
#pragma unroll
            for (int it = 0; it < 2; it++) {
                int u = tid + it * 256;
                int row = u >> 2, kc = u & 3;
                cp16(sbase + t * A_TILE + swoff(row, kc),
                     gsrc[t] + (size_t)row * HID + c * GBK + kc * 8);
            }
        }
        // B hi/lo: 256 rows x 4 kc = 1024 cp16 each
#pragma unroll
        for (int t = 0; t < 2; t++) {
#pragma unroll
            for (int it = 0; it < 4; it++) {
                int u = tid + it * 256;
                int row = u >> 2, kc = u & 3;
                cp16(sbase + 2 * A_TILE + t * B_TILE + swoff(row, kc),
                     gsrc[2 + t] + (size_t)row * HID + c * GBK + kc * 8);
            }
        }
        CP_COMMIT();
    }

    __device__ __forceinline__ void run(float acc[4][8][4]) {
#pragma unroll
        for (int i = 0; i < 4; i++)
#pragma unroll
            for (int j = 0; j < 8; j++)
#pragma unroll
                for (int e = 0; e < 4; e++) acc[i][j][e] = 0.f;

        prefetch(0, 0);
        prefetch(1, 1);

        const int a_row = lane & 15;
        const int a_kc  = lane >> 4;
        const int b_row = (lane & 7) + ((lane >> 4) << 3);
        const int b_kc  = (lane >> 3) & 1;
        const int NC = HID / GBK;

        int s = 0;
        for (int c = 0; c < NC; c++) {
            if (c + 2 < NC) { prefetch(c + 2, (c + 2) % GEMM_STAGES); cp_wait<2>(); }
            else if (c + 1 < NC) cp_wait<1>();
            else cp_wait<0>();
            __syncthreads();

            const uint32_t stg = sb + s * STAGE_BYTES;
#pragma unroll
            for (int kk = 0; kk < 2; kk++) {
                uint32_t ah[4][4], al[4][4];
#pragma unroll
                for (int mi = 0; mi < 4; mi++) {
                    int row = wm * 64 + mi * 16 + a_row;
                    uint32_t off = swoff(row, kk * 2 + a_kc);
                    ldmx4(ah[mi], stg + 0 * A_TILE + off);
                    ldmx4(al[mi], stg + 1 * A_TILE + off);
                }
#pragma unroll
                for (int nf = 0; nf < 4; nf++) {
                    uint32_t bh[4], bl[4];
                    int row = wn * 64 + nf * 16 + b_row;
                    uint32_t off = swoff(row, kk * 2 + b_kc);
                    ldmx4(bh, stg + 2 * A_TILE + 0 * B_TILE + off);
                    ldmx4(bl, stg + 2 * A_TILE + 1 * B_TILE + off);
#pragma unroll
                    for (int mi = 0; mi < 4; mi++)
#pragma unroll
                        for (int nq = 0; nq < 2; nq++) {
                            int ni = nf * 2 + nq, p = nq * 2;
                            mma16816(acc[mi][ni], ah[mi], bh[p], bh[p + 1]);
                            mma16816(acc[mi][ni], ah[mi], bl[p], bl[p + 1]);
                            mma16816(acc[mi][ni], al[mi], bh[p], bh[p + 1]);
                        }
                }
            }
            __syncthreads();
            s = (s + 1 == GEMM_STAGES) ? 0 : s + 1;
        }
    }
};

// -------- fused QKV projection: bx<16 -> Q, 16..19 -> K, 20..23 -> V(fp16 split)
__global__ __launch_bounds__(256, 1)
void gemm_qkv(const __nv_bfloat16* __restrict__ Ahi, const __nv_bfloat16* __restrict__ Alo,
              const __nv_bfloat16* __restrict__ WqH, const __nv_bfloat16* __restrict__ WqL,
              const __nv_bfloat16* __restrict__ WkH, const __nv_bfloat16* __restrict__ WkL,
              const __nv_bfloat16* __restrict__ WvH, const __nv_bfloat16* __restrict__ WvL,
              float* __restrict__ Cq, float* __restrict__ Ck,
              __half* __restrict__ VH, __half* __restrict__ VL) {
    extern __shared__ char sm[];
    const int bx = blockIdx.x;
    const int r0 = blockIdx.y * 128;

    int part, c0;
    const __nv_bfloat16 *BH, *BL;
    if (bx < 16)      { part = 0; c0 = bx * 256;        BH = WqH; BL = WqL; }
    else if (bx < 20) { part = 1; c0 = (bx - 16) * 256; BH = WkH; BL = WkL; }
    else              { part = 2; c0 = (bx - 20) * 256; BH = WvH; BL = WvL; }

    GemmCore core;
    core.sb = smem_u32(sm);
    core.tid = threadIdx.x;
    core.lane = core.tid & 31;
    core.wm = (core.tid >> 5) >> 2;
    core.wn = (core.tid >> 5) & 3;
    core.gsrc[0] = Ahi + (size_t)r0 * HID;
    core.gsrc[1] = Alo + (size_t)r0 * HID;
    core.gsrc[2] = BH + (size_t)c0 * HID;
    core.gsrc[3] = BL + (size_t)c0 * HID;

    float acc[4][8][4];
    core.run(acc);

    const int lane = core.lane, wm = core.wm, wn = core.wn;
    if (part == 0 || part == 1) {
        float* C = (part == 0) ? Cq : Ck;
        const int N = (part == 0) ? (NH * HD) : (NKV * HD);
#pragma unroll
        for (int mi = 0; mi < 4; mi++) {
            int gr = r0 + wm * 64 + mi * 16 + (lane >> 2);
#pragma unroll
            for (int ni = 0; ni < 8; ni++) {
                int gc = c0 + wn * 64 + ni * 8 + (lane & 3) * 2;
                *(float2*)&C[(size_t)gr * N + gc]       = make_float2(acc[mi][ni][0], acc[mi][ni][1]);
                *(float2*)&C[(size_t)(gr + 8) * N + gc] = make_float2(acc[mi][ni][2], acc[mi][ni][3]);
            }
        }
    } else {
        const int N = NKV * HD;
#pragma unroll
        for (int mi = 0; mi < 4; mi++) {
            int gr = r0 + wm * 64 + mi * 16 + (lane >> 2);
#pragma unroll
            for (int ni = 0; ni < 8; ni++) {
                int gc = c0 + wn * 64 + ni * 8 + (lane & 3) * 2;
                uint32_t hp, lp;
                split_pack_h(acc[mi][ni][0], acc[mi][ni][1], hp, lp);
                *(uint32_t*)&VH[(size_t)gr * N + gc] = hp;
                *(uint32_t*)&VL[(size_t)gr * N + gc] = lp;
                split_pack_h(acc[mi][ni][2], acc[mi][ni][3], hp, lp);
                *(uint32_t*)&VH[(size_t)(gr + 8) * N + gc] = hp;
                *(uint32_t*)&VL[(size_t)(gr + 8) * N + gc] = lp;
            }
        }
    }
}

// -------- generic GEMM (used for O projection) -------------------------------
__global__ __launch_bounds__(256, 1)
void gemm_hmma(const __nv_bfloat16* __restrict__ Ahi, const __nv_bfloat16* __restrict__ Alo,
               const __nv_bfloat16* __restrict__ Bhi, const __nv_bfloat16* __restrict__ Blo,
               float* __restrict__ C, int N) {
    extern __shared__ char sm[];
    const int r0 = blockIdx.y * 128;
    const int c0 = blockIdx.x * 256;

    GemmCore core;
    core.sb = smem_u32(sm);
    core.tid = threadIdx.x;
    core.lane = core.tid & 31;
    core.wm = (core.tid >> 5) >> 2;
    core.wn = (core.tid >> 5) & 3;
    core.gsrc[0] = Ahi + (size_t)r0 * HID;
    core.gsrc[1] = Alo + (size_t)r0 * HID;
    core.gsrc[2] = Bhi + (size_t)c0 * HID;
    core.gsrc[3] = Blo + (size_t)c0 * HID;

    float acc[4][8][4];
    core.run(acc);

    const int lane = core.lane, wm = core.wm, wn = core.wn;
#pragma unroll
    for (int mi = 0; mi < 4; mi++) {
        int gr = r0 + wm * 64 + mi * 16 + (lane >> 2);
#pragma unroll
        for (int ni = 0; ni < 8; ni++) {
            int gc = c0 + wn * 64 + ni * 8 + (lane & 3) * 2;
            *(float2*)&C[(size_t)gr * N + gc]       = make_float2(acc[mi][ni][0], acc[mi][ni][1]);
            *(float2*)&C[(size_t)(gr + 8) * N + gc] = make_float2(acc[mi][ni][2], acc[mi][ni][3]);
        }
    }
}

// =================== Flash attention: bf16x3 QK, fp16 softmax/PV ============
#define FS_QH 0
#define FS_QL 32768
#define FS_KV 65536
#define FS_STAGE 65536
#define FLASH_SMEM (FS_KV + 2 * FS_STAGE)   // 196608

__device__ __forceinline__ uint32_t fladdr(uint32_t base, int rb, int cb,
                                           int l7, int selr, int selc) {
    int r = rb + l7 + selr;
    int c = cb + selc;
    return base + r * 256 + (((c ^ (r & 7)) & 15) << 4);
}

__global__ __launch_bounds__(256, 1)
void flash_hmma(const __nv_bfloat16* __restrict__ Qhi, const __nv_bfloat16* __restrict__ Qlo,
                const __nv_bfloat16* __restrict__ Khi, const __nv_bfloat16* __restrict__ Klo,
                const __half* __restrict__ Vhi, const __half* __restrict__ Vlo,
                __nv_bfloat16* __restrict__ AOhi, __nv_bfloat16* __restrict__ AOlo) {
    extern __shared__ char fsm[];
    const uint32_t sb = smem_u32(fsm);
    const int tid = threadIdx.x;
    const int lane = tid & 31, wm = tid >> 5;
    const int gid = lane >> 2, tig = lane & 3;
    const int l7 = lane & 7, selr = ((lane >> 3) & 1) << 3, selc = lane >> 4;

    const int qb = (int)(gridDim.x - 1 - blockIdx.x);
    const int h = blockIdx.y;
    const int kv = h >> 2;
    const int q0 = qb * 128;
    const int njb = 2 * (qb + 1);

#pragma unroll
    for (int i = 0; i < 8; i++) {
        int u = tid + i * 256;
        int row = u >> 4, c = u & 15;
        uint32_t so = (row << 8) + (((c ^ (row & 7))) << 4);
        const size_t gi = (size_t)(q0 + row) * (NH * HD) + h * HD + c * 8;
        cp16(sb + FS_QH + so, Qhi + gi);
        cp16(sb + FS_QL + so, Qlo + gi);
    }
    const void* kvsrc[4] = {Khi, Klo, Vhi, Vlo};
    auto prefetch_kv = [&](int jb, int s) {
        uint32_t sbase = sb + FS_KV + s * FS_STAGE;
#pragma unroll
        for (int t = 0; t < 4; t++) {
#pragma unroll
            for (int i = 0; i < 4; i++) {
                int u = tid + i * 256;
                int row = u >> 4, c = u & 15;
                uint32_t so = (row << 8) + (((c ^ (row & 7))) << 4);
                cp16(sbase + t * 16384 + so,
                     (const char*)kvsrc[t] + ((size_t)(jb * 64 + row) * (NKV * HD) + kv * HD + c * 8) * 2);
            }
        }
        CP_COMMIT();
    };
    prefetch_kv(0, 0);

    float oacc[16][4];
#pragma unroll
    for (int j = 0; j < 16; j++)
#pragma unroll
        for (int e = 0; e < 4; e++) oacc[j][e] = 0.f;
    float m0 = -1e30f, m1 = -1e30f, l0 = 0.f, l1 = 0.f;

    const int wrow0 = q0 + wm * 16;

    for (int jb = 0; jb < njb; jb++) {
        if (jb + 1 < njb) { prefetch_kv(jb + 1, (jb + 1) & 1); cp_wait<1>(); }
        else cp_wait<0>();
        __syncthreads();

        const int k0 = jb * 64;
        const bool skip = (k0 > wrow0 + 15);
        if (!skip) {
            const uint32_t stg = sb + FS_KV + (jb & 1) * FS_STAGE;
            float sacc[8][4];
#pragma unroll
            for (int j = 0; j < 8; j++)
#pragma unroll
                for (int e = 0; e < 4; e++) sacc[j][e] = 0.f;
#pragma unroll
            for (int ks = 0; ks < 8; ks++) {
                uint32_t ah[4], al[4];
                uint32_t aa = fladdr(sb + FS_QH, wm * 16, 2 * ks, l7, selr, selc);
                ldmx4(ah, aa);
                ldmx4(al, aa + (FS_QL - FS_QH));
#pragma unroll
                for (int g4 = 0; g4 < 4; g4++) {
                    uint32_t bh[4], bl[4];
                    uint32_t ba = fladdr(stg, 16 * g4, 2 * ks, l7, selr, selc);
                    ldmx4(bh, ba);
                    ldmx4(bl, ba + 16384);
                    mma16816(sacc[2 * g4],     ah, bh[0], bh[2]);
                    mma16816(sacc[2 * g4],     ah, bl[0], bl[2]);
                    mma16816(sacc[2 * g4],     al, bh[0], bh[2]);
                    mma16816(sacc[2 * g4 + 1], ah, bh[1], bh[3]);
                    mma16816(sacc[2 * g4 + 1], ah, bl[1], bl[3]);
                    mma16816(sacc[2 * g4 + 1], al, bh[1], bh[3]);
                }
            }
            if (k0 + 63 > wrow0) {
                int row0 = wrow0 + gid;
#pragma unroll
                for (int j = 0; j < 8; j++) {
                    int col = k0 + 8 * j + 2 * tig;
                    if (col > row0)         sacc[j][0] = -1e30f;
                    if (col + 1 > row0)     sacc[j][1] = -1e30f;
                    if (col > row0 + 8)     sacc[j][2] = -1e30f;
                    if (col + 1 > row0 + 8) sacc[j][3] = -1e30f;
                }
            }
            float tm0 = -1e30f, tm1 = -1e30f;
#pragma unroll
            for (int j = 0; j < 8; j++) {
                tm0 = fmaxf(tm0, fmaxf(sacc[j][0], sacc[j][1]));
                tm1 = fmaxf(tm1, fmaxf(sacc[j][2], sacc[j][3]));
            }
            tm0 = fmaxf(tm0, __shfl_xor_sync(0xffffffffu, tm0, 1));
            tm0 = fmaxf(tm0, __shfl_xor_sync(0xffffffffu, tm0, 2));
            tm1 = fmaxf(tm1, __shfl_xor_sync(0xffffffffu, tm1, 1));
            tm1 = fmaxf(tm1, __shfl_xor_sync(0xffffffffu, tm1, 2));
            float mn0 = fmaxf(m0, tm0), mn1 = fmaxf(m1, tm1);
            float a0 = ex2f(m0 - mn0), a1 = ex2f(m1 - mn1);
            m0 = mn0; m1 = mn1;

            uint32_t pp[8][2];
            float rs0 = 0.f, rs1 = 0.f;
#pragma unroll
            for (int j = 0; j < 8; j++) {
                pp[j][0] = ex2_f16x2(sacc[j][0] - mn0, sacc[j][1] - mn0);
                pp[j][1] = ex2_f16x2(sacc[j][2] - mn1, sacc[j][3] - mn1);
                float2 f0 = __half22float2(*reinterpret_cast<__half2*>(&pp[j][0]));
                float2 f1 = __half22float2(*reinterpret_cast<__half2*>(&pp[j][1]));
                rs0 += f0.x + f0.y;
                rs1 += f1.x + f1.y;
            }
            rs0 += __shfl_xor_sync(0xffffffffu, rs0, 1);
            rs0 += __shfl_xor_sync(0xffffffffu, rs0, 2);
            rs1 += __shfl_xor_sync(0xffffffffu, rs1, 1);
            rs1 += __shfl_xor_sync(0xffffffffu, rs1, 2);
            l0 = l0 * a0 + rs0;
            l1 = l1 * a1 + rs1;
#pragma unroll
            for (int j = 0; j < 16; j++) {
                oacc[j][0] *= a0; oacc[j][1] *= a0;
                oacc[j][2] *= a1; oacc[j][3] *= a1;
            }
#pragma unroll
            for (int ks = 0; ks < 4; ks++) {
                uint32_t pf[4] = { pp[2*ks][0], pp[2*ks][1], pp[2*ks+1][0], pp[2*ks+1][1] };
#pragma unroll
                for (int g = 0; g < 8; g++) {
                    uint32_t vh[4], vl[4];
                    uint32_t va = fladdr(stg + 32768, 16 * ks, 2 * g, l7, selr, selc);
                    ldmx4t(vh, va);
                    ldmx4t(vl, va + 16384);
                    mma16816h(oacc[2 * g],     pf, vh[0], vh[1]);
                    mma16816h(oacc[2 * g],     pf, vl[0], vl[1]);
                    mma16816h(oacc[2 * g + 1], pf, vh[2], vh[3]);
                    mma16816h(oacc[2 * g + 1], pf, vl[2], vl[3]);
                }
            }
        }
        __syncthreads();
    }

    const float inv0 = 1.f / l0, inv1 = 1.f / l1;
    const int row0 = wrow0 + gid;
#pragma unroll
    for (int j = 0; j < 16; j++) {
        size_t d = (size_t)h * HD + 8 * j + 2 * tig;
        uint32_t hp, lp;
        split_pack(oacc[j][0] * inv0, oacc[j][1] * inv0, hp, lp);
        *(uint32_t*)&AOhi[(size_t)row0 * (NH * HD) + d] = hp;
        *(uint32_t*)&AOlo[(size_t)row0 * (NH * HD) + d] = lp;
        split_pack(oacc[j][2] * inv1, oacc[j][3] * inv1, hp, lp);
        *(uint32_t*)&AOhi[(size_t)(row0 + 8) * (NH * HD) + d] = hp;
        *(uint32_t*)&AOlo[(size_t)(row0 + 8) * (NH * HD) + d] = lp;
    }
}

// ---------------- launch ----------------------------------------------------
extern "C" void kernel_launch(void* const* d_in, const int* in_sizes, int n_in,
                              void* d_out, int out_size) {
    const float* hs   = (const float*)d_in[0];
    const float* cosb = (const float*)d_in[1];
    const float* sinb = (const float*)d_in[2];
    const float* Wq   = (const float*)d_in[4];
    const float* Wk   = (const float*)d_in[5];
    const float* Wv   = (const float*)d_in[6];
    const float* Wo   = (const float*)d_in[7];
    float* out = (float*)d_out;

    float *Qp, *Kp;
    cudaGetSymbolAddress((void**)&Qp,  g_Q);
    cudaGetSymbolAddress((void**)&Kp,  g_K);
    __nv_bfloat16 *hsH, *hsL, *wqH, *wqL, *wkH, *wkL, *wvH, *wvL, *woH, *woL, *aoH, *aoL;
    __nv_bfloat16 *qH, *qL, *kH, *kL;
    __half *vH, *vL;
    cudaGetSymbolAddress((void**)&hsH, g_hs_hi); cudaGetSymbolAddress((void**)&hsL, g_hs_lo);
    cudaGetSymbolAddress((void**)&wqH, g_wq_hi); cudaGetSymbolAddress((void**)&wqL, g_wq_lo);
    cudaGetSymbolAddress((void**)&wkH, g_wk_hi); cudaGetSymbolAddress((void**)&wkL, g_wk_lo);
    cudaGetSymbolAddress((void**)&wvH, g_wv_hi); cudaGetSymbolAddress((void**)&wvL, g_wv_lo);
    cudaGetSymbolAddress((void**)&woH, g_wo_hi); cudaGetSymbolAddress((void**)&woL, g_wo_lo);
    cudaGetSymbolAddress((void**)&aoH, g_ao_hi); cudaGetSymbolAddress((void**)&aoL, g_ao_lo);
    cudaGetSymbolAddress((void**)&qH,  g_q_hi);  cudaGetSymbolAddress((void**)&qL,  g_q_lo);
    cudaGetSymbolAddress((void**)&kH,  g_k_hi);  cudaGetSymbolAddress((void**)&kL,  g_k_lo);
    cudaGetSymbolAddress((void**)&vH,  g_v_hi);  cudaGetSymbolAddress((void**)&vL,  g_v_lo);

    cudaFuncSetAttribute(gemm_qkv,  cudaFuncAttributeMaxDynamicSharedMemorySize, GEMM_SMEM);
    cudaFuncSetAttribute(gemm_hmma, cudaFuncAttributeMaxDynamicSharedMemorySize, GEMM_SMEM);
    cudaFuncSetAttribute(flash_hmma, cudaFuncAttributeMaxDynamicSharedMemorySize, FLASH_SMEM);

    auto split = [](const float* src, __nv_bfloat16* hi, __nv_bfloat16* lo, int n) {
        int n4 = n / 4;
        split_f32<<<(n4 + 255) / 256, 256>>>((const float4*)src, (uint2*)hi, (uint2*)lo, n4);
    };

    // splits
    split(hs, hsH, hsL, S_LEN * HID);
    split(Wq, wqH, wqL, HID * HID);
    split(Wk, wkH, wkL, NKV * HD * HID);
    split(Wv, wvH, wvL, NKV * HD * HID);
    split(Wo, woH, woL, HID * HID);

    // fused QKV projection (CTA 128x256; V fp16-split in epilogue)
    gemm_qkv<<<dim3(24, S_LEN / 128), 256, GEMM_SMEM>>>(
        hsH, hsL, wqH, wqL, wkH, wkL, wvH, wvL, Qp, Kp, vH, vL);

    // RoPE + split (Q pre-scaled by softmax_scale * log2(e))
    const float SC = 0.08838834764831845f * 1.4426950408889634f;
    rope_split<<<(S_LEN * NH  * 32 + 255) / 256, 256>>>(Qp, cosb, sinb, qH, qL, NH,  SC);
    rope_split<<<(S_LEN * NKV * 32 + 255) / 256, 256>>>(Kp, cosb, sinb, kH, kL, NKV, 1.0f);

    // attention
    flash_hmma<<<dim3(S_LEN / 128, NH), 256, FLASH_SMEM>>>(qH, qL, kH, kL, vH, vL, aoH, aoL);

    // output projection (CTA 128x256)
    gemm_hmma<<<dim3((NH * HD) / 256, S_LEN / 128), 256, GEMM_SMEM>>>(aoH, aoL, woH, woL, out, NH * HD);
}

// round 9
// speedup vs baseline: 1.0271x; 1.0271x over previous
#include <cuda_runtime.h>
#include <cuda_bf16.h>
#include <cuda_fp16.h>
#include <math.h>
#include <cstdint>

#define S_LEN 2048
#define HID   4096
#define NH    32
#define NKV   8
#define HD    128

// ---------------- scratch (static device globals; no allocations) -----------
__device__ float g_Q [S_LEN * NH  * HD];
__device__ float g_K [S_LEN * NKV * HD];

__device__ __nv_bfloat16 g_hs_hi[S_LEN * HID],      g_hs_lo[S_LEN * HID];
__device__ __nv_bfloat16 g_wq_hi[HID * HID],        g_wq_lo[HID * HID];
__device__ __nv_bfloat16 g_wk_hi[NKV * HD * HID],   g_wk_lo[NKV * HD * HID];
__device__ __nv_bfloat16 g_wv_hi[NKV * HD * HID],   g_wv_lo[NKV * HD * HID];
__device__ __nv_bfloat16 g_wo_hi[HID * HID],        g_wo_lo[HID * HID];
__device__ __nv_bfloat16 g_ao_hi[S_LEN * HID],      g_ao_lo[S_LEN * HID];
__device__ __nv_bfloat16 g_q_hi[S_LEN * NH  * HD],  g_q_lo[S_LEN * NH  * HD];
__device__ __nv_bfloat16 g_k_hi[S_LEN * NKV * HD],  g_k_lo[S_LEN * NKV * HD];
__device__ __half        g_v_hi[S_LEN * NKV * HD],  g_v_lo[S_LEN * NKV * HD];

// ---------------- common PTX helpers ----------------------------------------
__device__ __forceinline__ uint32_t smem_u32(const void* p) {
    uint32_t a;
    asm("{ .reg .u64 t; cvta.to.shared.u64 t, %1; cvt.u32.u64 %0, t; }" : "=r"(a) : "l"(p));
    return a;
}
__device__ __forceinline__ void cp16(uint32_t dst, const void* src) {
    asm volatile("cp.async.cg.shared.global [%0], [%1], 16;" :: "r"(dst), "l"(src) : "memory");
}
#define CP_COMMIT() asm volatile("cp.async.commit_group;" ::: "memory")
template <int N> __device__ __forceinline__ void cp_wait() {
    asm volatile("cp.async.wait_group %0;" :: "n"(N) : "memory");
}
__device__ __forceinline__ void ldmx4(uint32_t* r, uint32_t addr) {
    asm volatile("ldmatrix.sync.aligned.m8n8.x4.shared.b16 {%0,%1,%2,%3}, [%4];"
                 : "=r"(r[0]), "=r"(r[1]), "=r"(r[2]), "=r"(r[3]) : "r"(addr));
}
__device__ __forceinline__ void ldmx4t(uint32_t* r, uint32_t addr) {
    asm volatile("ldmatrix.sync.aligned.m8n8.x4.trans.shared.b16 {%0,%1,%2,%3}, [%4];"
                 : "=r"(r[0]), "=r"(r[1]), "=r"(r[2]), "=r"(r[3]) : "r"(addr));
}
__device__ __forceinline__ void mma16816(float* d, const uint32_t* a, uint32_t b0, uint32_t b1) {
    asm volatile(
        "mma.sync.aligned.m16n8k16.row.col.f32.bf16.bf16.f32 "
        "{%0,%1,%2,%3}, {%4,%5,%6,%7}, {%8,%9}, {%0,%1,%2,%3};"
        : "+f"(d[0]), "+f"(d[1]), "+f"(d[2]), "+f"(d[3])
        : "r"(a[0]), "r"(a[1]), "r"(a[2]), "r"(a[3]), "r"(b0), "r"(b1));
}
__device__ __forceinline__ void mma16816h(float* d, const uint32_t* a, uint32_t b0, uint32_t b1) {
    asm volatile(
        "mma.sync.aligned.m16n8k16.row.col.f32.f16.f16.f32 "
        "{%0,%1,%2,%3}, {%4,%5,%6,%7}, {%8,%9}, {%0,%1,%2,%3};"
        : "+f"(d[0]), "+f"(d[1]), "+f"(d[2]), "+f"(d[3])
        : "r"(a[0]), "r"(a[1]), "r"(a[2]), "r"(a[3]), "r"(b0), "r"(b1));
}
__device__ __forceinline__ uint32_t pack_bf16(float a, float b) {
    return ((uint32_t)__bfloat16_as_ushort(__float2bfloat16_rn(b)) << 16) |
           __bfloat16_as_ushort(__float2bfloat16_rn(a));
}
__device__ __forceinline__ void split_pack(float a, float b, uint32_t& hp, uint32_t& lp) {
    __nv_bfloat16 ha = __float2bfloat16_rn(a), hb = __float2bfloat16_rn(b);
    hp = ((uint32_t)__bfloat16_as_ushort(hb) << 16) | __bfloat16_as_ushort(ha);
    lp = pack_bf16(a - __bfloat162float(ha), b - __bfloat162float(hb));
}
__device__ __forceinline__ void split_pack_h(float a, float b, uint32_t& hp, uint32_t& lp) {
    __half ha = __float2half_rn(a), hb = __float2half_rn(b);
    hp = ((uint32_t)__half_as_ushort(hb) << 16) | __half_as_ushort(ha);
    __half la = __float2half_rn(a - __half2float(ha));
    __half lb = __float2half_rn(b - __half2float(hb));
    lp = ((uint32_t)__half_as_ushort(lb) << 16) | __half_as_ushort(la);
}
__device__ __forceinline__ float ex2f(float x) {
    float y;
    asm("ex2.approx.ftz.f32 %0, %1;" : "=f"(y) : "f"(x));
    return y;
}
__device__ __forceinline__ uint32_t ex2_f16x2(float a, float b) {
    uint32_t p;
    asm("cvt.rn.f16x2.f32 %0, %1, %2;" : "=r"(p) : "f"(b), "f"(a));
    asm("ex2.approx.f16x2 %0, %0;" : "+r"(p));
    return p;
}

// ---------------- split kernels ---------------------------------------------
__global__ void split_f32(const float4* __restrict__ x,
                          uint2* __restrict__ hi, uint2* __restrict__ lo, int n4) {
    int i = blockIdx.x * blockDim.x + threadIdx.x;
    if (i >= n4) return;
    float4 v = x[i];
    float xs[4] = {v.x, v.y, v.z, v.w};
    unsigned short h[4], l[4];
#pragma unroll
    for (int j = 0; j < 4; j++) {
        __nv_bfloat16 hb = __float2bfloat16_rn(xs[j]);
        float r = xs[j] - __bfloat162float(hb);
        h[j] = __bfloat16_as_ushort(hb);
        l[j] = __bfloat16_as_ushort(__float2bfloat16_rn(r));
    }
    hi[i] = make_uint2(((uint32_t)h[1] << 16) | h[0], ((uint32_t)h[3] << 16) | h[2]);
    lo[i] = make_uint2(((uint32_t)l[1] << 16) | l[0], ((uint32_t)l[3] << 16) | l[2]);
}

__global__ void rope_split(const float* __restrict__ X, const float* __restrict__ cosb,
                           const float* __restrict__ sinb,
                           __nv_bfloat16* __restrict__ hi, __nv_bfloat16* __restrict__ lo,
                           int nheads, float sc) {
    int idx = blockIdx.x * blockDim.x + threadIdx.x;
    int total = S_LEN * nheads * 32;
    if (idx >= total) return;
    int d = (idx & 31) * 2;
    int hh = (idx >> 5) % nheads;
    int s = idx / (32 * nheads);
    size_t base = (size_t)s * nheads * HD + hh * HD;
    float2 x1 = *(const float2*)(X + base + d);
    float2 x2 = *(const float2*)(X + base + d + 64);
    float2 c1 = *(const float2*)(cosb + s * HD + d);
    float2 s1 = *(const float2*)(sinb + s * HD + d);
    float2 c2 = *(const float2*)(cosb + s * HD + d + 64);
    float2 s2 = *(const float2*)(sinb + s * HD + d + 64);
    float o[4] = { (x1.x * c1.x - x2.x * s1.x) * sc, (x1.y * c1.y - x2.y * s1.y) * sc,
                   (x2.x * c2.x + x1.x * s2.x) * sc, (x2.y * c2.y + x1.y * s2.y) * sc };
    uint32_t hp0, lp0, hp1, lp1;
    split_pack(o[0], o[1], hp0, lp0);
    split_pack(o[2], o[3], hp1, lp1);
    *(uint32_t*)(hi + base + d)      = hp0;
    *(uint32_t*)(hi + base + d + 64) = hp1;
    *(uint32_t*)(lo + base + d)      = lp0;
    *(uint32_t*)(lo + base + d + 64) = lp1;
}

// =================== HMMA split-bf16 GEMM (R7 config: 128x128, occ 2) =======
#define GBK 32
#define TILE_BYTES 8192
#define STAGE_BYTES (4 * TILE_BYTES)
#define GEMM_STAGES 3
#define GEMM_SMEM (GEMM_STAGES * STAGE_BYTES)   // 96 KB

__device__ __forceinline__ uint32_t swoff(int row, int kc) {
    return (uint32_t)(row * 64 + ((kc ^ ((row >> 1) & 3)) << 4));
}

struct GemmCore {
    uint32_t sb;
    int tid, lane, wm, wn;
    const __nv_bfloat16* gsrc[4];

    __device__ __forceinline__ void prefetch(int c, int s) {
        uint32_t sbase = sb + s * STAGE_BYTES;
#pragma unroll
        for (int t = 0; t < 4; t++) {
#pragma unroll
            for (int it = 0; it < 2; it++) {
                int u = tid + it * 256;
                int row = u >> 2, kc = u & 3;
                cp16(sbase + t * TILE_BYTES + swoff(row, kc),
                     gsrc[t] + (size_t)row * HID + c * GBK + kc * 8);
            }
        }
        CP_COMMIT();
    }

    __device__ __forceinline__ void run(float acc[4][4][4]) {
#pragma unroll
        for (int i = 0; i < 4; i++)
#pragma unroll
            for (int j = 0; j < 4; j++)
#pragma unroll
                for (int e = 0; e < 4; e++) acc[i][j][e] = 0.f;

        prefetch(0, 0);
        prefetch(1, 1);

        const int a_row = lane & 15;
        const int a_kc  = lane >> 4;
        const int b_row = (lane & 7) + ((lane >> 4) << 3);
        const int b_kc  = (lane >> 3) & 1;
        const int NC = HID / GBK;

        int s = 0;
        for (int c = 0; c < NC; c++) {
            if (c + 2 < NC) { prefetch(c + 2, (c + 2) % GEMM_STAGES); cp_wait<2>(); }
            else if (c + 1 < NC) cp_wait<1>();
            else cp_wait<0>();
            __syncthreads();

            const uint32_t stg = sb + s * STAGE_BYTES;
#pragma unroll
            for (int kk = 0; kk < 2; kk++) {
                uint32_t ah[4][4], al[4][4];
#pragma unroll
                for (int mi = 0; mi < 4; mi++) {
                    int row = wm * 64 + mi * 16 + a_row;
                    uint32_t off = swoff(row, kk * 2 + a_kc);
                    ldmx4(ah[mi], stg + 0 * TILE_BYTES + off);
                    ldmx4(al[mi], stg + 1 * TILE_BYTES + off);
                }
#pragma unroll
                for (int nf = 0; nf < 2; nf++) {
                    uint32_t bh[4], bl[4];
                    int row = wn * 32 + nf * 16 + b_row;
                    uint32_t off = swoff(row, kk * 2 + b_kc);
                    ldmx4(bh, stg + 2 * TILE_BYTES + off);
                    ldmx4(bl, stg + 3 * TILE_BYTES + off);
#pragma unroll
                    for (int mi = 0; mi < 4; mi++)
#pragma unroll
                        for (int nq = 0; nq < 2; nq++) {
                            int ni = nf * 2 + nq, p = nq * 2;
                            mma16816(acc[mi][ni], ah[mi], bh[p], bh[p + 1]);
                            mma16816(acc[mi][ni], ah[mi], bl[p], bl[p + 1]);
                            mma16816(acc[mi][ni], al[mi], bh[p], bh[p + 1]);
                        }
                }
            }
            __syncthreads();
            s = (s + 1 == GEMM_STAGES) ? 0 : s + 1;
        }
    }
};

// -------- fused QKV projection: bx<32 -> Q, 32..39 -> K, 40..47 -> V(fp16 split)
__global__ __launch_bounds__(256, 2)
void gemm_qkv(const __nv_bfloat16* __restrict__ Ahi, const __nv_bfloat16* __restrict__ Alo,
              const __nv_bfloat16* __restrict__ WqH, const __nv_bfloat16* __restrict__ WqL,
              const __nv_bfloat16* __restrict__ WkH, const __nv_bfloat16* __restrict__ WkL,
              const __nv_bfloat16* __restrict__ WvH, const __nv_bfloat16* __restrict__ WvL,
              float* __restrict__ Cq, float* __restrict__ Ck,
              __half* __restrict__ VH, __half* __restrict__ VL) {
    extern __shared__ char sm[];
    const int bx = blockIdx.x;
    const int r0 = blockIdx.y * 128;

    int part, c0;
    const __nv_bfloat16 *BH, *BL;
    if (bx < 32)      { part = 0; c0 = bx * 128;        BH = WqH; BL = WqL; }
    else if (bx < 40) { part = 1; c0 = (bx - 32) * 128; BH = WkH; BL = WkL; }
    else              { part = 2; c0 = (bx - 40) * 128; BH = WvH; BL = WvL; }

    GemmCore core;
    core.sb = smem_u32(sm);
    core.tid = threadIdx.x;
    core.lane = core.tid & 31;
    core.wm = (core.tid >> 5) >> 2;
    core.wn = (core.tid >> 5) & 3;
    core.gsrc[0] = Ahi + (size_t)r0 * HID;
    core.gsrc[1] = Alo + (size_t)r0 * HID;
    core.gsrc[2] = BH + (size_t)c0 * HID;
    core.gsrc[3] = BL + (size_t)c0 * HID;

    float acc[4][4][4];
    core.run(acc);

    const int lane = core.lane, wm = core.wm, wn = core.wn;
    if (part == 0 || part == 1) {
        float* C = (part == 0) ? Cq : Ck;
        const int N = (part == 0) ? (NH * HD) : (NKV * HD);
#pragma unroll
        for (int mi = 0; mi < 4; mi++) {
            int gr = r0 + wm * 64 + mi * 16 + (lane >> 2);
#pragma unroll
            for (int ni = 0; ni < 4; ni++) {
                int gc = c0 + wn * 32 + ni * 8 + (lane & 3) * 2;
                *(float2*)&C[(size_t)gr * N + gc]       = make_float2(acc[mi][ni][0], acc[mi][ni][1]);
                *(float2*)&C[(size_t)(gr + 8) * N + gc] = make_float2(acc[mi][ni][2], acc[mi][ni][3]);
            }
        }
    } else {
        const int N = NKV * HD;
#pragma unroll
        for (int mi = 0; mi < 4; mi++) {
            int gr = r0 + wm * 64 + mi * 16 + (lane >> 2);
#pragma unroll
            for (int ni = 0; ni < 4; ni++) {
                int gc = c0 + wn * 32 + ni * 8 + (lane & 3) * 2;
                uint32_t hp, lp;
                split_pack_h(acc[mi][ni][0], acc[mi][ni][1], hp, lp);
                *(uint32_t*)&VH[(size_t)gr * N + gc] = hp;
                *(uint32_t*)&VL[(size_t)gr * N + gc] = lp;
                split_pack_h(acc[mi][ni][2], acc[mi][ni][3], hp, lp);
                *(uint32_t*)&VH[(size_t)(gr + 8) * N + gc] = hp;
                *(uint32_t*)&VL[(size_t)(gr + 8) * N + gc] = lp;
            }
        }
    }
}

// -------- generic GEMM (used for O projection) -------------------------------
__global__ __launch_bounds__(256, 2)
void gemm_hmma(const __nv_bfloat16* __restrict__ Ahi, const __nv_bfloat16* __restrict__ Alo,
               const __nv_bfloat16* __restrict__ Bhi, const __nv_bfloat16* __restrict__ Blo,
               float* __restrict__ C, int N) {
    extern __shared__ char sm[];
    const int r0 = blockIdx.y * 128;
    const int c0 = blockIdx.x * 128;

    GemmCore core;
    core.sb = smem_u32(sm);
    core.tid = threadIdx.x;
    core.lane = core.tid & 31;
    core.wm = (core.tid >> 5) >> 2;
    core.wn = (core.tid >> 5) & 3;
    core.gsrc[0] = Ahi + (size_t)r0 * HID;
    core.gsrc[1] = Alo + (size_t)r0 * HID;
    core.gsrc[2] = Bhi + (size_t)c0 * HID;
    core.gsrc[3] = Blo + (size_t)c0 * HID;

    float acc[4][4][4];
    core.run(acc);

    const int lane = core.lane, wm = core.wm, wn = core.wn;
#pragma unroll
    for (int mi = 0; mi < 4; mi++) {
        int gr = r0 + wm * 64 + mi * 16 + (lane >> 2);
#pragma unroll
        for (int ni = 0; ni < 4; ni++) {
            int gc = c0 + wn * 32 + ni * 8 + (lane & 3) * 2;
            *(float2*)&C[(size_t)gr * N + gc]       = make_float2(acc[mi][ni][0], acc[mi][ni][1]);
            *(float2*)&C[(size_t)(gr + 8) * N + gc] = make_float2(acc[mi][ni][2], acc[mi][ni][3]);
        }
    }
}

// =================== Flash attention: bf16x3 QK (Q in regs), fp16 PV ========
#define FS_QH 0
#define FS_QL 32768
#define FS_KV 65536
#define FS_STAGE 65536
#define FLASH_SMEM (FS_KV + 2 * FS_STAGE)   // 196608

__device__ __forceinline__ uint32_t fladdr(uint32_t base, int rb, int cb,
                                           int l7, int selr, int selc) {
    int r = rb + l7 + selr;
    int c = cb + selc;
    return base + r * 256 + (((c ^ (r & 7)) & 15) << 4);
}

__global__ __launch_bounds__(256, 1)
void flash_hmma(const __nv_bfloat16* __restrict__ Qhi, const __nv_bfloat16* __restrict__ Qlo,
                const __nv_bfloat16* __restrict__ Khi, const __nv_bfloat16* __restrict__ Klo,
                const __half* __restrict__ Vhi, const __half* __restrict__ Vlo,
                __nv_bfloat16* __restrict__ AOhi, __nv_bfloat16* __restrict__ AOlo) {
    extern __shared__ char fsm[];
    const uint32_t sb = smem_u32(fsm);
    const int tid = threadIdx.x;
    const int lane = tid & 31, wm = tid >> 5;
    const int gid = lane >> 2, tig = lane & 3;
    const int l7 = lane & 7, selr = ((lane >> 3) & 1) << 3, selc = lane >> 4;

    const int qb = (int)(gridDim.x - 1 - blockIdx.x);
    const int h = blockIdx.y;
    const int kv = h >> 2;
    const int q0 = qb * 128;
    const int njb = 2 * (qb + 1);

    // Q tile -> smem (own commit group)
#pragma unroll
    for (int i = 0; i < 8; i++) {
        int u = tid + i * 256;
        int row = u >> 4, c = u & 15;
        uint32_t so = (row << 8) + (((c ^ (row & 7))) << 4);
        const size_t gi = (size_t)(q0 + row) * (NH * HD) + h * HD + c * 8;
        cp16(sb + FS_QH + so, Qhi + gi);
        cp16(sb + FS_QL + so, Qlo + gi);
    }
    CP_COMMIT();

    const void* kvsrc[4] = {Khi, Klo, Vhi, Vlo};
    auto prefetch_kv = [&](int jb, int s) {
        uint32_t sbase = sb + FS_KV + s * FS_STAGE;
#pragma unroll
        for (int t = 0; t < 4; t++) {
#pragma unroll
            for (int i = 0; i < 4; i++) {
                int u = tid + i * 256;
                int row = u >> 4, c = u & 15;
                uint32_t so = (row << 8) + (((c ^ (row & 7))) << 4);
                cp16(sbase + t * 16384 + so,
                     (const char*)kvsrc[t] + ((size_t)(jb * 64 + row) * (NKV * HD) + kv * HD + c * 8) * 2);
            }
        }
        CP_COMMIT();
    };
    prefetch_kv(0, 0);

    // hoist Q fragments into registers (Q group done when <=1 group pending)
    uint32_t qh[8][4], ql[8][4];
    cp_wait<1>();
    __syncthreads();
#pragma unroll
    for (int ks = 0; ks < 8; ks++) {
        uint32_t aa = fladdr(sb + FS_QH, wm * 16, 2 * ks, l7, selr, selc);
        ldmx4(qh[ks], aa);
        ldmx4(ql[ks], aa + (FS_QL - FS_QH));
    }

    float oacc[16][4];
#pragma unroll
    for (int j = 0; j < 16; j++)
#pragma unroll
        for (int e = 0; e < 4; e++) oacc[j][e] = 0.f;
    float m0 = -1e30f, m1 = -1e30f, l0 = 0.f, l1 = 0.f;

    const int wrow0 = q0 + wm * 16;

    for (int jb = 0; jb < njb; jb++) {
        if (jb + 1 < njb) { prefetch_kv(jb + 1, (jb + 1) & 1); cp_wait<1>(); }
        else cp_wait<0>();
        __syncthreads();

        const int k0 = jb * 64;
        const bool skip = (k0 > wrow0 + 15);
        if (!skip) {
            const uint32_t stg = sb + FS_KV + (jb & 1) * FS_STAGE;
            float sacc[8][4];
#pragma unroll
            for (int j = 0; j < 8; j++)
#pragma unroll
                for (int e = 0; e < 4; e++) sacc[j][e] = 0.f;
#pragma unroll
            for (int ks = 0; ks < 8; ks++) {
#pragma unroll
                for (int g4 = 0; g4 < 4; g4++) {
                    uint32_t bh[4], bl[4];
                    uint32_t ba = fladdr(stg, 16 * g4, 2 * ks, l7, selr, selc);
                    ldmx4(bh, ba);
                    ldmx4(bl, ba + 16384);
                    mma16816(sacc[2 * g4],     qh[ks], bh[0], bh[2]);
                    mma16816(sacc[2 * g4],     qh[ks], bl[0], bl[2]);
                    mma16816(sacc[2 * g4],     ql[ks], bh[0], bh[2]);
                    mma16816(sacc[2 * g4 + 1], qh[ks], bh[1], bh[3]);
                    mma16816(sacc[2 * g4 + 1], qh[ks], bl[1], bl[3]);
                    mma16816(sacc[2 * g4 + 1], ql[ks], bh[1], bh[3]);
                }
            }
            if (k0 + 63 > wrow0) {
                int row0 = wrow0 + gid;
#pragma unroll
                for (int j = 0; j < 8; j++) {
                    int col = k0 + 8 * j + 2 * tig;
                    if (col > row0)         sacc[j][0] = -1e30f;
                    if (col + 1 > row0)     sacc[j][1] = -1e30f;
                    if (col > row0 + 8)     sacc[j][2] = -1e30f;
                    if (col + 1 > row0 + 8) sacc[j][3] = -1e30f;
                }
            }
            float tm0 = -1e30f, tm1 = -1e30f;
#pragma unroll
            for (int j = 0; j < 8; j++) {
                tm0 = fmaxf(tm0, fmaxf(sacc[j][0], sacc[j][1]));
                tm1 = fmaxf(tm1, fmaxf(sacc[j][2], sacc[j][3]));
            }
            tm0 = fmaxf(tm0, __shfl_xor_sync(0xffffffffu, tm0, 1));
            tm0 = fmaxf(tm0, __shfl_xor_sync(0xffffffffu, tm0, 2));
            tm1 = fmaxf(tm1, __shfl_xor_sync(0xffffffffu, tm1, 1));
            tm1 = fmaxf(tm1, __shfl_xor_sync(0xffffffffu, tm1, 2));
            float mn0 = fmaxf(m0, tm0), mn1 = fmaxf(m1, tm1);
            float a0 = ex2f(m0 - mn0), a1 = ex2f(m1 - mn1);
            m0 = mn0; m1 = mn1;

            uint32_t pp[8][2];
            float rs0 = 0.f, rs1 = 0.f;
#pragma unroll
            for (int j = 0; j < 8; j++) {
                pp[j][0] = ex2_f16x2(sacc[j][0] - mn0, sacc[j][1] - mn0);
                pp[j][1] = ex2_f16x2(sacc[j][2] - mn1, sacc[j][3] - mn1);
                float2 f0 = __half22float2(*reinterpret_cast<__half2*>(&pp[j][0]));
                float2 f1 = __half22float2(*reinterpret_cast<__half2*>(&pp[j][1]));
                rs0 += f0.x + f0.y;
                rs1 += f1.x + f1.y;
            }
            rs0 += __shfl_xor_sync(0xffffffffu, rs0, 1);
            rs0 += __shfl_xor_sync(0xffffffffu, rs0, 2);
            rs1 += __shfl_xor_sync(0xffffffffu, rs1, 1);
            rs1 += __shfl_xor_sync(0xffffffffu, rs1, 2);
            l0 = l0 * a0 + rs0;
            l1 = l1 * a1 + rs1;
#pragma unroll
            for (int j = 0; j < 16; j++) {
                oacc[j][0] *= a0; oacc[j][1] *= a0;
                oacc[j][2] *= a1; oacc[j][3] *= a1;
            }
#pragma unroll
            for (int ks = 0; ks < 4; ks++) {
                uint32_t pf[4] = { pp[2*ks][0], pp[2*ks][1], pp[2*ks+1][0], pp[2*ks+1][1] };
#pragma unroll
                for (int g = 0; g < 8; g++) {
                    uint32_t vh[4], vl[4];
                    uint32_t va = fladdr(stg + 32768, 16 * ks, 2 * g, l7, selr, selc);
                    ldmx4t(vh, va);
                    ldmx4t(vl, va + 16384);
                    mma16816h(oacc[2 * g],     pf, vh[0], vh[1]);
                    mma16816h(oacc[2 * g],     pf, vl[0], vl[1]);
                    mma16816h(oacc[2 * g + 1], pf, vh[2], vh[3]);
                    mma16816h(oacc[2 * g + 1], pf, vl[2], vl[3]);
                }
            }
        }
        __syncthreads();
    }

    const float inv0 = 1.f / l0, inv1 = 1.f / l1;
    const int row0 = wrow0 + gid;
#pragma unroll
    for (int j = 0; j < 16; j++) {
        size_t d = (size_t)h * HD + 8 * j + 2 * tig;
        uint32_t hp, lp;
        split_pack(oacc[j][0] * inv0, oacc[j][1] * inv0, hp, lp);
        *(uint32_t*)&AOhi[(size_t)row0 * (NH * HD) + d] = hp;
        *(uint32_t*)&AOlo[(size_t)row0 * (NH * HD) + d] = lp;
        split_pack(oacc[j][2] * inv1, oacc[j][3] * inv1, hp, lp);
        *(uint32_t*)&AOhi[(size_t)(row0 + 8) * (NH * HD) + d] = hp;
        *(uint32_t*)&AOlo[(size_t)(row0 + 8) * (NH * HD) + d] = lp;
    }
}

// ---------------- launch ----------------------------------------------------
extern "C" void kernel_launch(void* const* d_in, const int* in_sizes, int n_in,
                              void* d_out, int out_size) {
    const float* hs   = (const float*)d_in[0];
    const float* cosb = (const float*)d_in[1];
    const float* sinb = (const float*)d_in[2];
    const float* Wq   = (const float*)d_in[4];
    const float* Wk   = (const float*)d_in[5];
    const float* Wv   = (const float*)d_in[6];
    const float* Wo   = (const float*)d_in[7];
    float* out = (float*)d_out;

    float *Qp, *Kp;
    cudaGetSymbolAddress((void**)&Qp,  g_Q);
    cudaGetSymbolAddress((void**)&Kp,  g_K);
    __nv_bfloat16 *hsH, *hsL, *wqH, *wqL, *wkH, *wkL, *wvH, *wvL, *woH, *woL, *aoH, *aoL;
    __nv_bfloat16 *qH, *qL, *kH, *kL;
    __half *vH, *vL;
    cudaGetSymbolAddress((void**)&hsH, g_hs_hi); cudaGetSymbolAddress((void**)&hsL, g_hs_lo);
    cudaGetSymbolAddress((void**)&wqH, g_wq_hi); cudaGetSymbolAddress((void**)&wqL, g_wq_lo);
    cudaGetSymbolAddress((void**)&wkH, g_wk_hi); cudaGetSymbolAddress((void**)&wkL, g_wk_lo);
    cudaGetSymbolAddress((void**)&wvH, g_wv_hi); cudaGetSymbolAddress((void**)&wvL, g_wv_lo);
    cudaGetSymbolAddress((void**)&woH, g_wo_hi); cudaGetSymbolAddress((void**)&woL, g_wo_lo);
    cudaGetSymbolAddress((void**)&aoH, g_ao_hi); cudaGetSymbolAddress((void**)&aoL, g_ao_lo);
    cudaGetSymbolAddress((void**)&qH,  g_q_hi);  cudaGetSymbolAddress((void**)&qL,  g_q_lo);
    cudaGetSymbolAddress((void**)&kH,  g_k_hi);  cudaGetSymbolAddress((void**)&kL,  g_k_lo);
    cudaGetSymbolAddress((void**)&vH,  g_v_hi);  cudaGetSymbolAddress((void**)&vL,  g_v_lo);

    cudaFuncSetAttribute(gemm_qkv,  cudaFuncAttributeMaxDynamicSharedMemorySize, GEMM_SMEM);
    cudaFuncSetAttribute(gemm_hmma, cudaFuncAttributeMaxDynamicSharedMemorySize, GEMM_SMEM);
    cudaFuncSetAttribute(flash_hmma, cudaFuncAttributeMaxDynamicSharedMemorySize, FLASH_SMEM);

    auto split = [](const float* src, __nv_bfloat16* hi, __nv_bfloat16* lo, int n) {
        int n4 = n / 4;
        split_f32<<<(n4 + 255) / 256, 256>>>((const float4*)src, (uint2*)hi, (uint2*)lo, n4);
    };

    // splits
    split(hs, hsH, hsL, S_LEN * HID);
    split(Wq, wqH, wqL, HID * HID);
    split(Wk, wkH, wkL, NKV * HD * HID);
    split(Wv, wvH, wvL, NKV * HD * HID);
    split(Wo, woH, woL, HID * HID);

    // fused QKV projection (128x128 occ-2; V fp16-split in epilogue)
    gemm_qkv<<<dim3(48, S_LEN / 128), 256, GEMM_SMEM>>>(
        hsH, hsL, wqH, wqL, wkH, wkL, wvH, wvL, Qp, Kp, vH, vL);

    // RoPE + split (Q pre-scaled by softmax_scale * log2(e))
    const float SC = 0.08838834764831845f * 1.4426950408889634f;
    rope_split<<<(S_LEN * NH  * 32 + 255) / 256, 256>>>(Qp, cosb, sinb, qH, qL, NH,  SC);
    rope_split<<<(S_LEN * NKV * 32 + 255) / 256, 256>>>(Kp, cosb, sinb, kH, kL, NKV, 1.0f);

    // attention (Q fragments hoisted to registers)
    flash_hmma<<<dim3(S_LEN / 128, NH), 256, FLASH_SMEM>>>(qH, qL, kH, kL, vH, vL, aoH, aoL);

    // output projection (128x128 occ-2)
    gemm_hmma<<<dim3((NH * HD) / 128, S_LEN / 128), 256, GEMM_SMEM>>>(aoH, aoL, woH, woL, out, NH * HD);
}